// round 5
// baseline (speedup 1.0000x reference)
#include <cuda_runtime.h>
#include <cuda_bf16.h>
#include <math.h>

// Problem constants
#define B_   4
#define N_   512
#define FIN  64
#define FOUT 128

// Scratch (allocation-free rule: __device__ globals)
static __device__ float g_pi [B_ * N_ * FOUT];   // nodes @ edge_W[:,F:].T
static __device__ float g_pjb[B_ * N_ * FOUT];   // nodes @ edge_W[:,:F].T + edge_b
static __device__ float g_h  [B_ * N_ * FOUT];   // full MLP output

__device__ __forceinline__ float celu1(float x) {
    return x > 0.f ? x : expm1f(x);
}

// ---------------------------------------------------------------------------
// K1: per node-row (b*N+n): pi, pjb, and the 3-layer CELU MLP.
// grid = B*N blocks, 128 threads (one per output feature f).
// ---------------------------------------------------------------------------
__global__ __launch_bounds__(128) void k1_pernode(
    const float* __restrict__ nodes,
    const float* __restrict__ eW, const float* __restrict__ eb,
    const float* __restrict__ W0, const float* __restrict__ b0,
    const float* __restrict__ W1, const float* __restrict__ b1,
    const float* __restrict__ W2, const float* __restrict__ b2)
{
    const int row = blockIdx.x;          // b*N + n
    const int f   = threadIdx.x;         // 0..127
    __shared__ float x[FIN];
    __shared__ float h0[FOUT];
    __shared__ float h1[FOUT];

    if (f < FIN) x[f] = nodes[(size_t)row * FIN + f];
    __syncthreads();

    // pj (cols 0..63) and pi (cols 64..127) of edge_W row f
    {
        const float4* wr = (const float4*)(eW + (size_t)f * (2 * FIN));
        float pj = 0.f, pi = 0.f;
        #pragma unroll
        for (int k = 0; k < 16; k++) {
            float4 wj = wr[k];
            float4 wi = wr[k + 16];
            float x0 = x[4*k], x1 = x[4*k+1], x2 = x[4*k+2], x3 = x[4*k+3];
            pj += wj.x*x0 + wj.y*x1 + wj.z*x2 + wj.w*x3;
            pi += wi.x*x0 + wi.y*x1 + wi.z*x2 + wi.w*x3;
        }
        g_pjb[(size_t)row * FOUT + f] = pj + eb[f];
        g_pi [(size_t)row * FOUT + f] = pi;
    }

    // MLP layer 0: [F_OUT,F_IN]
    {
        const float4* wr = (const float4*)(W0 + (size_t)f * FIN);
        float a = b0[f];
        #pragma unroll
        for (int k = 0; k < 16; k++) {
            float4 w = wr[k];
            a += w.x*x[4*k] + w.y*x[4*k+1] + w.z*x[4*k+2] + w.w*x[4*k+3];
        }
        h0[f] = celu1(a);
    }
    __syncthreads();

    // MLP layer 1: [F_OUT,F_OUT]
    {
        const float4* wr = (const float4*)(W1 + (size_t)f * FOUT);
        float a = b1[f];
        #pragma unroll
        for (int k = 0; k < 32; k++) {
            float4 w = wr[k];
            a += w.x*h0[4*k] + w.y*h0[4*k+1] + w.z*h0[4*k+2] + w.w*h0[4*k+3];
        }
        h1[f] = celu1(a);
    }
    __syncthreads();

    // MLP layer 2: [F_OUT,F_OUT]
    {
        const float4* wr = (const float4*)(W2 + (size_t)f * FOUT);
        float a = b2[f];
        #pragma unroll
        for (int k = 0; k < 32; k++) {
            float4 w = wr[k];
            a += w.x*h1[4*k] + w.y*h1[4*k+1] + w.z*h1[4*k+2] + w.w*h1[4*k+3];
        }
        g_h[(size_t)row * FOUT + f] = a;
    }
}

// ---------------------------------------------------------------------------
// K2: edges writer. 16x16 (i,j) tile per block; pi/pjb rows staged in SMEM so
// each row is read once per block (L2 read traffic ~64MB vs 512MB naive).
// Each warp writes one full 128-float edge row per iteration via STG.128.
// grid = (N/16, N/16, B), 256 threads.
// ---------------------------------------------------------------------------
__global__ __launch_bounds__(256) void k2_edges(
    const float* __restrict__ sk, float* __restrict__ edges)
{
    const int b  = blockIdx.z;
    const int i0 = blockIdx.y * 16;
    const int j0 = blockIdx.x * 16;
    const int tid = threadIdx.x;

    __shared__ float4 spi [16][32];
    __shared__ float4 spjb[16][32];
    __shared__ float  ssk [16][16];

    // stage pi / pjb tiles (16 consecutive rows of 32 float4 each)
    const float4* gpi  = (const float4*)(g_pi  + ((size_t)(b * N_ + i0)) * FOUT);
    const float4* gpjb = (const float4*)(g_pjb + ((size_t)(b * N_ + j0)) * FOUT);
    #pragma unroll
    for (int t = tid; t < 512; t += 256) {
        spi [t >> 5][t & 31] = gpi [t];
        spjb[t >> 5][t & 31] = gpjb[t];
    }
    // stage skeleton tile
    {
        int ii = tid >> 4, jj = tid & 15;
        ssk[ii][jj] = sk[((size_t)(b * N_ + i0 + ii)) * N_ + j0 + jj];
    }
    __syncthreads();

    const int lane = tid & 31;
    const int w    = tid >> 5;
    float4* __restrict__ e4 = (float4*)edges;

    #pragma unroll 8
    for (int p = w; p < 256; p += 8) {
        int ii = p >> 4, jj = p & 15;
        float  s = ssk[ii][jj];
        float4 a = spi [ii][lane];
        float4 c = spjb[jj][lane];
        float4 e;
        e.x = (a.x + c.x) * s;
        e.y = (a.y + c.y) * s;
        e.z = (a.z + c.z) * s;
        e.w = (a.w + c.w) * s;
        size_t idx = ((size_t)(b * N_ + i0 + ii) * N_ + (j0 + jj)) * (FOUT / 4) + lane;
        e4[idx] = e;
    }
}

// ---------------------------------------------------------------------------
// K3: nodes_new via factored reduction (never touches edges), then node_W
// GEMV + bias + h, write final output block.
//   nn[b,j,f] = pjb[b,j,f]*S[b,j] + sum_i sk[b,i,j]*pi[b,i,f]
//   out1[b,j,f] = h[b,j,f] + sum_k nn[b,j,k]*node_W[f,k] + node_b[f]
// Block handles (b, 8 consecutive j). grid = (N/8, B), 128 threads (f).
// ---------------------------------------------------------------------------
__global__ __launch_bounds__(128) void k3_reduce(
    const float* __restrict__ sk,
    const float* __restrict__ nW, const float* __restrict__ nb,
    float* __restrict__ out1)
{
    const int b  = blockIdx.y;
    const int j0 = blockIdx.x * 8;
    const int f  = threadIdx.x;

    __shared__ float ssk[64][8];
    __shared__ float nn[8][FOUT];
    __shared__ float ssum[8];

    float acc[8];
    #pragma unroll
    for (int jj = 0; jj < 8; jj++) acc[jj] = 0.f;
    float ssum_local = 0.f;

    const float* pib = g_pi + (size_t)b * N_ * FOUT + f;

    for (int i0 = 0; i0 < N_; i0 += 64) {
        __syncthreads();
        // stage sk chunk [64 i][8 j]
        #pragma unroll
        for (int t = f; t < 512; t += 128) {
            int ii = t >> 3, jj = t & 7;
            ssk[ii][jj] = sk[((size_t)(b * N_ + i0 + ii)) * N_ + j0 + jj];
        }
        __syncthreads();

        // column sums (threads 0..7 only; redundant work avoided elsewhere)
        if (f < 8) {
            float t = 0.f;
            #pragma unroll
            for (int ii = 0; ii < 64; ii++) t += ssk[ii][f];
            ssum_local += t;
        }

        #pragma unroll 8
        for (int ii = 0; ii < 64; ii++) {
            float p = pib[(size_t)(i0 + ii) * FOUT];
            #pragma unroll
            for (int jj = 0; jj < 8; jj++)
                acc[jj] += ssk[ii][jj] * p;
        }
    }

    if (f < 8) ssum[f] = ssum_local;
    __syncthreads();

    const float* pjbr = g_pjb + ((size_t)(b * N_ + j0)) * FOUT;
    #pragma unroll
    for (int jj = 0; jj < 8; jj++)
        nn[jj][f] = acc[jj] + pjbr[(size_t)jj * FOUT + f] * ssum[jj];
    __syncthreads();

    // node_W GEMV for the 8 rows
    float o[8];
    #pragma unroll
    for (int jj = 0; jj < 8; jj++) o[jj] = nb[f];
    const float4* nwr = (const float4*)(nW + (size_t)f * FOUT);
    #pragma unroll 8
    for (int k = 0; k < 32; k++) {
        float4 w = nwr[k];
        #pragma unroll
        for (int jj = 0; jj < 8; jj++)
            o[jj] += w.x*nn[jj][4*k] + w.y*nn[jj][4*k+1]
                   + w.z*nn[jj][4*k+2] + w.w*nn[jj][4*k+3];
    }

    const float* hr = g_h + ((size_t)(b * N_ + j0)) * FOUT;
    #pragma unroll
    for (int jj = 0; jj < 8; jj++)
        out1[((size_t)(b * N_ + j0 + jj)) * FOUT + f] = o[jj] + hr[(size_t)jj * FOUT + f];
}

// ---------------------------------------------------------------------------
extern "C" void kernel_launch(void* const* d_in, const int* in_sizes, int n_in,
                              void* d_out, int out_size)
{
    const float* nodes = (const float*)d_in[0];
    const float* sk    = (const float*)d_in[1];
    const float* eW    = (const float*)d_in[2];
    const float* eb    = (const float*)d_in[3];
    const float* nW    = (const float*)d_in[4];
    const float* nb    = (const float*)d_in[5];
    const float* W0    = (const float*)d_in[6];
    const float* b0    = (const float*)d_in[7];
    const float* W1    = (const float*)d_in[8];
    const float* b1    = (const float*)d_in[9];
    const float* W2    = (const float*)d_in[10];
    const float* b2    = (const float*)d_in[11];

    float* out1  = (float*)d_out;                                   // [B,N,F_OUT]
    float* edges = (float*)d_out + (size_t)B_ * N_ * FOUT;          // [B,N,N,F_OUT]

    k1_pernode<<<B_ * N_, 128>>>(nodes, eW, eb, W0, b0, W1, b1, W2, b2);

    dim3 g2(N_ / 16, N_ / 16, B_);
    k2_edges<<<g2, 256>>>(sk, edges);

    dim3 g3(N_ / 8, B_);
    k3_reduce<<<g3, 128>>>(sk, nW, nb, out1);
}

// round 6
// speedup vs baseline: 1.7045x; 1.7045x over previous
#include <cuda_runtime.h>
#include <cuda_bf16.h>
#include <math.h>

// Problem constants
#define B_   4
#define N_   512
#define FIN  64
#define FOUT 128
#define NCH  8           // i-chunks for split reduction (64 i per chunk)

// Scratch (allocation-free rule: __device__ globals)
static __device__ float g_pi   [B_ * N_ * FOUT];          // nodes @ edge_W[:,F:].T
static __device__ float g_pjb  [B_ * N_ * FOUT];          // nodes @ edge_W[:,:F].T + edge_b
static __device__ float g_h    [B_ * N_ * FOUT];          // full MLP output
static __device__ float g_part [B_ * NCH * N_ * FOUT];    // partial sk^T@pi  (8MB)
static __device__ float g_partS[B_ * NCH * N_];           // partial column sums of sk

__device__ __forceinline__ float celu1(float x) {
    return x > 0.f ? x : expm1f(x);
}

// ---------------------------------------------------------------------------
// K1: 8 node rows per block, weight-stationary with 8-way ILP.
// grid = B*N/8 = 256 blocks, 128 threads (one per output feature f).
// ---------------------------------------------------------------------------
__global__ __launch_bounds__(128) void k1_pernode(
    const float* __restrict__ nodes,
    const float* __restrict__ eW, const float* __restrict__ eb,
    const float* __restrict__ W0, const float* __restrict__ b0,
    const float* __restrict__ W1, const float* __restrict__ b1,
    const float* __restrict__ W2, const float* __restrict__ b2)
{
    const int row0 = blockIdx.x * 8;
    const int f    = threadIdx.x;        // 0..127

    __shared__ float x [8][FIN];         // 2KB
    __shared__ float h0[8][FOUT];        // 4KB
    __shared__ float h1[8][FOUT];        // 4KB

    // cooperative load of 8 rows of x (128 float4 total)
    {
        float4*       xs = (float4*)&x[0][0];
        const float4* gx = (const float4*)(nodes + (size_t)row0 * FIN);
        xs[f] = gx[f];
    }
    __syncthreads();

    // --- edge projections: pj & pi for 8 rows ---
    {
        const float4* wr = (const float4*)(eW + (size_t)f * (2 * FIN));
        float accj[8], acci[8];
        #pragma unroll
        for (int r = 0; r < 8; r++) { accj[r] = 0.f; acci[r] = 0.f; }
        #pragma unroll
        for (int k = 0; k < 16; k++) {
            float4 wj = wr[k];
            float4 wi = wr[k + 16];
            #pragma unroll
            for (int r = 0; r < 8; r++) {
                float4 xv = ((const float4*)x[r])[k];
                accj[r] += wj.x*xv.x + wj.y*xv.y + wj.z*xv.z + wj.w*xv.w;
                acci[r] += wi.x*xv.x + wi.y*xv.y + wi.z*xv.z + wi.w*xv.w;
            }
        }
        const float ebf = eb[f];
        #pragma unroll
        for (int r = 0; r < 8; r++) {
            g_pjb[(size_t)(row0 + r) * FOUT + f] = accj[r] + ebf;
            g_pi [(size_t)(row0 + r) * FOUT + f] = acci[r];
        }
    }

    // --- MLP layer 0: [F_OUT, F_IN] + CELU ---
    {
        const float4* wr = (const float4*)(W0 + (size_t)f * FIN);
        const float   bf = b0[f];
        float a[8];
        #pragma unroll
        for (int r = 0; r < 8; r++) a[r] = bf;
        #pragma unroll
        for (int k = 0; k < 16; k++) {
            float4 w = wr[k];
            #pragma unroll
            for (int r = 0; r < 8; r++) {
                float4 xv = ((const float4*)x[r])[k];
                a[r] += w.x*xv.x + w.y*xv.y + w.z*xv.z + w.w*xv.w;
            }
        }
        #pragma unroll
        for (int r = 0; r < 8; r++) h0[r][f] = celu1(a[r]);
    }
    __syncthreads();

    // --- MLP layer 1: [F_OUT, F_OUT] + CELU ---
    {
        const float4* wr = (const float4*)(W1 + (size_t)f * FOUT);
        const float   bf = b1[f];
        float a[8];
        #pragma unroll
        for (int r = 0; r < 8; r++) a[r] = bf;
        #pragma unroll
        for (int k = 0; k < 32; k++) {
            float4 w = wr[k];
            #pragma unroll
            for (int r = 0; r < 8; r++) {
                float4 hv = ((const float4*)h0[r])[k];
                a[r] += w.x*hv.x + w.y*hv.y + w.z*hv.z + w.w*hv.w;
            }
        }
        #pragma unroll
        for (int r = 0; r < 8; r++) h1[r][f] = celu1(a[r]);
    }
    __syncthreads();

    // --- MLP layer 2: [F_OUT, F_OUT] -> g_h ---
    {
        const float4* wr = (const float4*)(W2 + (size_t)f * FOUT);
        const float   bf = b2[f];
        float a[8];
        #pragma unroll
        for (int r = 0; r < 8; r++) a[r] = bf;
        #pragma unroll
        for (int k = 0; k < 32; k++) {
            float4 w = wr[k];
            #pragma unroll
            for (int r = 0; r < 8; r++) {
                float4 hv = ((const float4*)h1[r])[k];
                a[r] += w.x*hv.x + w.y*hv.y + w.z*hv.z + w.w*hv.w;
            }
        }
        #pragma unroll
        for (int r = 0; r < 8; r++)
            g_h[(size_t)(row0 + r) * FOUT + f] = a[r];
    }
}

// ---------------------------------------------------------------------------
// K2: edges writer. 16x16 (i,j) tile per block; pi/pjb rows staged in SMEM.
// Pure streaming store of 512MB — at the DRAM floor.
// grid = (N/16, N/16, B), 256 threads.
// ---------------------------------------------------------------------------
__global__ __launch_bounds__(256) void k2_edges(
    const float* __restrict__ sk, float* __restrict__ edges)
{
    const int b  = blockIdx.z;
    const int i0 = blockIdx.y * 16;
    const int j0 = blockIdx.x * 16;
    const int tid = threadIdx.x;

    __shared__ float4 spi [16][32];
    __shared__ float4 spjb[16][32];
    __shared__ float  ssk [16][16];

    const float4* gpi  = (const float4*)(g_pi  + ((size_t)(b * N_ + i0)) * FOUT);
    const float4* gpjb = (const float4*)(g_pjb + ((size_t)(b * N_ + j0)) * FOUT);
    #pragma unroll
    for (int t = tid; t < 512; t += 256) {
        spi [t >> 5][t & 31] = gpi [t];
        spjb[t >> 5][t & 31] = gpjb[t];
    }
    {
        int ii = tid >> 4, jj = tid & 15;
        ssk[ii][jj] = sk[((size_t)(b * N_ + i0 + ii)) * N_ + j0 + jj];
    }
    __syncthreads();

    const int lane = tid & 31;
    const int w    = tid >> 5;
    float4* __restrict__ e4 = (float4*)edges;

    #pragma unroll 8
    for (int p = w; p < 256; p += 8) {
        int ii = p >> 4, jj = p & 15;
        float  s = ssk[ii][jj];
        float4 a = spi [ii][lane];
        float4 c = spjb[jj][lane];
        float4 e;
        e.x = (a.x + c.x) * s;
        e.y = (a.y + c.y) * s;
        e.z = (a.z + c.z) * s;
        e.w = (a.w + c.w) * s;
        size_t idx = ((size_t)(b * N_ + i0 + ii) * N_ + (j0 + jj)) * (FOUT / 4) + lane;
        e4[idx] = e;
    }
}

// ---------------------------------------------------------------------------
// K3a: split-i partial reduction (deterministic, no atomics).
//   part[b,c,j,f] = sum_{i in chunk c} sk[b,i,j] * pi[b,i,f]
//   partS[b,c,j]  = sum_{i in chunk c} sk[b,i,j]
// grid = (N/8, NCH, B) = 2048 blocks, 128 threads (f).
// ---------------------------------------------------------------------------
__global__ __launch_bounds__(128) void k3a_partial(const float* __restrict__ sk)
{
    const int b  = blockIdx.z;
    const int c  = blockIdx.y;
    const int j0 = blockIdx.x * 8;
    const int f  = threadIdx.x;
    const int i0 = c * 64;

    __shared__ float ssk[64][8];

    #pragma unroll
    for (int t = f; t < 512; t += 128) {
        int ii = t >> 3, jj = t & 7;
        ssk[ii][jj] = sk[((size_t)(b * N_ + i0 + ii)) * N_ + j0 + jj];
    }
    __syncthreads();

    float acc[8];
    #pragma unroll
    for (int jj = 0; jj < 8; jj++) acc[jj] = 0.f;

    const float* pib = g_pi + ((size_t)(b * N_ + i0)) * FOUT + f;
    #pragma unroll 8
    for (int ii = 0; ii < 64; ii++) {
        float p = pib[(size_t)ii * FOUT];
        #pragma unroll
        for (int jj = 0; jj < 8; jj++) acc[jj] += ssk[ii][jj] * p;
    }

    float* outp = g_part + (((size_t)(b * NCH + c) * N_) + j0) * FOUT + f;
    #pragma unroll
    for (int jj = 0; jj < 8; jj++) outp[(size_t)jj * FOUT] = acc[jj];

    if (f < 8) {
        float s = 0.f;
        #pragma unroll
        for (int ii = 0; ii < 64; ii++) s += ssk[ii][f];
        g_partS[((size_t)(b * NCH + c)) * N_ + j0 + f] = s;
    }
}

// ---------------------------------------------------------------------------
// K3b: fold partials, add pjb*S, node_W GEMV + bias + h, write final output.
// grid = (N/8, B), 128 threads (f).
// ---------------------------------------------------------------------------
__global__ __launch_bounds__(128) void k3b_final(
    const float* __restrict__ nW, const float* __restrict__ nb,
    float* __restrict__ out1)
{
    const int b  = blockIdx.y;
    const int j0 = blockIdx.x * 8;
    const int f  = threadIdx.x;

    __shared__ float nn[8][FOUT];
    __shared__ float S[8];

    if (f < 8) {
        float s = 0.f;
        #pragma unroll
        for (int c = 0; c < NCH; c++)
            s += g_partS[((size_t)(b * NCH + c)) * N_ + j0 + f];
        S[f] = s;
    }

    float acc[8];
    #pragma unroll
    for (int jj = 0; jj < 8; jj++) acc[jj] = 0.f;
    #pragma unroll
    for (int c = 0; c < NCH; c++) {
        const float* pr = g_part + (((size_t)(b * NCH + c) * N_) + j0) * FOUT + f;
        #pragma unroll
        for (int jj = 0; jj < 8; jj++) acc[jj] += pr[(size_t)jj * FOUT];
    }
    __syncthreads();

    const float* pjbr = g_pjb + ((size_t)(b * N_ + j0)) * FOUT;
    #pragma unroll
    for (int jj = 0; jj < 8; jj++)
        nn[jj][f] = acc[jj] + pjbr[(size_t)jj * FOUT + f] * S[jj];
    __syncthreads();

    float o[8];
    const float nbf = nb[f];
    #pragma unroll
    for (int jj = 0; jj < 8; jj++) o[jj] = nbf;
    const float4* nwr = (const float4*)(nW + (size_t)f * FOUT);
    #pragma unroll 8
    for (int k = 0; k < 32; k++) {
        float4 w = nwr[k];
        #pragma unroll
        for (int jj = 0; jj < 8; jj++)
            o[jj] += w.x*nn[jj][4*k] + w.y*nn[jj][4*k+1]
                   + w.z*nn[jj][4*k+2] + w.w*nn[jj][4*k+3];
    }

    const float* hr = g_h + ((size_t)(b * N_ + j0)) * FOUT;
    #pragma unroll
    for (int jj = 0; jj < 8; jj++)
        out1[((size_t)(b * N_ + j0 + jj)) * FOUT + f] = o[jj] + hr[(size_t)jj * FOUT + f];
}

// ---------------------------------------------------------------------------
extern "C" void kernel_launch(void* const* d_in, const int* in_sizes, int n_in,
                              void* d_out, int out_size)
{
    const float* nodes = (const float*)d_in[0];
    const float* sk    = (const float*)d_in[1];
    const float* eW    = (const float*)d_in[2];
    const float* eb    = (const float*)d_in[3];
    const float* nW    = (const float*)d_in[4];
    const float* nb    = (const float*)d_in[5];
    const float* W0    = (const float*)d_in[6];
    const float* b0    = (const float*)d_in[7];
    const float* W1    = (const float*)d_in[8];
    const float* b1    = (const float*)d_in[9];
    const float* W2    = (const float*)d_in[10];
    const float* b2    = (const float*)d_in[11];

    float* out1  = (float*)d_out;                            // [B,N,F_OUT]
    float* edges = (float*)d_out + (size_t)B_ * N_ * FOUT;   // [B,N,N,F_OUT]

    k1_pernode<<<(B_ * N_) / 8, 128>>>(nodes, eW, eb, W0, b0, W1, b1, W2, b2);

    dim3 g3a(N_ / 8, NCH, B_);
    k3a_partial<<<g3a, 128>>>(sk);

    dim3 g2(N_ / 16, N_ / 16, B_);
    k2_edges<<<g2, 256>>>(sk, edges);

    dim3 g3b(N_ / 8, B_);
    k3b_final<<<g3b, 128>>>(nW, nb, out1);
}

// round 8
// speedup vs baseline: 1.8551x; 1.0883x over previous
#include <cuda_runtime.h>
#include <cuda_bf16.h>
#include <math.h>

// Problem constants
#define B_   4
#define N_   512
#define FIN  64
#define FOUT 128
#define NCH  8           // i-chunks (64 i per chunk) — matches K2 grid.y

// Scratch (allocation-free rule: __device__ globals)
static __device__ float g_pi   [B_ * N_ * FOUT];          // nodes @ edge_W[:,F:].T
static __device__ float g_pjb  [B_ * N_ * FOUT];          // nodes @ edge_W[:,:F].T + edge_b
static __device__ float g_h    [B_ * N_ * FOUT];          // full MLP output
static __device__ float g_part [B_ * NCH * N_ * FOUT];    // partial sum_i edges (8MB)

__device__ __forceinline__ float celu1(float x) {
    return x > 0.f ? x : expm1f(x);
}

// ---------------------------------------------------------------------------
// K1: 8 node rows per block, weight-stationary with 8-way ILP.
// grid = B*N/8 = 256 blocks, 128 threads (one per output feature f).
// ---------------------------------------------------------------------------
__global__ __launch_bounds__(128) void k1_pernode(
    const float* __restrict__ nodes,
    const float* __restrict__ eW, const float* __restrict__ eb,
    const float* __restrict__ W0, const float* __restrict__ b0,
    const float* __restrict__ W1, const float* __restrict__ b1,
    const float* __restrict__ W2, const float* __restrict__ b2)
{
    const int row0 = blockIdx.x * 8;
    const int f    = threadIdx.x;        // 0..127

    __shared__ float x [8][FIN];
    __shared__ float h0[8][FOUT];
    __shared__ float h1[8][FOUT];

    {
        float4*       xs = (float4*)&x[0][0];
        const float4* gx = (const float4*)(nodes + (size_t)row0 * FIN);
        xs[f] = gx[f];
    }
    __syncthreads();

    // --- edge projections: pj & pi for 8 rows ---
    {
        const float4* wr = (const float4*)(eW + (size_t)f * (2 * FIN));
        float accj[8], acci[8];
        #pragma unroll
        for (int r = 0; r < 8; r++) { accj[r] = 0.f; acci[r] = 0.f; }
        #pragma unroll
        for (int k = 0; k < 16; k++) {
            float4 wj = wr[k];
            float4 wi = wr[k + 16];
            #pragma unroll
            for (int r = 0; r < 8; r++) {
                float4 xv = ((const float4*)x[r])[k];
                accj[r] += wj.x*xv.x + wj.y*xv.y + wj.z*xv.z + wj.w*xv.w;
                acci[r] += wi.x*xv.x + wi.y*xv.y + wi.z*xv.z + wi.w*xv.w;
            }
        }
        const float ebf = eb[f];
        #pragma unroll
        for (int r = 0; r < 8; r++) {
            g_pjb[(size_t)(row0 + r) * FOUT + f] = accj[r] + ebf;
            g_pi [(size_t)(row0 + r) * FOUT + f] = acci[r];
        }
    }

    // --- MLP layer 0 + CELU ---
    {
        const float4* wr = (const float4*)(W0 + (size_t)f * FIN);
        const float   bf = b0[f];
        float a[8];
        #pragma unroll
        for (int r = 0; r < 8; r++) a[r] = bf;
        #pragma unroll
        for (int k = 0; k < 16; k++) {
            float4 w = wr[k];
            #pragma unroll
            for (int r = 0; r < 8; r++) {
                float4 xv = ((const float4*)x[r])[k];
                a[r] += w.x*xv.x + w.y*xv.y + w.z*xv.z + w.w*xv.w;
            }
        }
        #pragma unroll
        for (int r = 0; r < 8; r++) h0[r][f] = celu1(a[r]);
    }
    __syncthreads();

    // --- MLP layer 1 + CELU ---
    {
        const float4* wr = (const float4*)(W1 + (size_t)f * FOUT);
        const float   bf = b1[f];
        float a[8];
        #pragma unroll
        for (int r = 0; r < 8; r++) a[r] = bf;
        #pragma unroll
        for (int k = 0; k < 32; k++) {
            float4 w = wr[k];
            #pragma unroll
            for (int r = 0; r < 8; r++) {
                float4 hv = ((const float4*)h0[r])[k];
                a[r] += w.x*hv.x + w.y*hv.y + w.z*hv.z + w.w*hv.w;
            }
        }
        #pragma unroll
        for (int r = 0; r < 8; r++) h1[r][f] = celu1(a[r]);
    }
    __syncthreads();

    // --- MLP layer 2 -> g_h ---
    {
        const float4* wr = (const float4*)(W2 + (size_t)f * FOUT);
        const float   bf = b2[f];
        float a[8];
        #pragma unroll
        for (int r = 0; r < 8; r++) a[r] = bf;
        #pragma unroll
        for (int k = 0; k < 32; k++) {
            float4 w = wr[k];
            #pragma unroll
            for (int r = 0; r < 8; r++) {
                float4 hv = ((const float4*)h1[r])[k];
                a[r] += w.x*hv.x + w.y*hv.y + w.z*hv.z + w.w*hv.w;
            }
        }
        #pragma unroll
        for (int r = 0; r < 8; r++)
            g_h[(size_t)(row0 + r) * FOUT + f] = a[r];
    }
}

// ---------------------------------------------------------------------------
// K2: edges writer WITH fused i-partial reduction.
// Tile: 64 (i) x 16 (j) per block. grid = (N/16, N/64, B) = 32x8x4, 256 thr.
// Warp w owns j-columns {w, w+8} for all 64 i: accumulates sum_i of the FULL
// edge values (includes pjb term) next to the streaming stores.
// ---------------------------------------------------------------------------
__global__ __launch_bounds__(256) void k2_edges(
    const float* __restrict__ sk, float* __restrict__ edges)
{
    const int b  = blockIdx.z;
    const int iy = blockIdx.y;           // i-chunk 0..7
    const int i0 = iy * 64;
    const int j0 = blockIdx.x * 16;
    const int tid = threadIdx.x;

    __shared__ float4 spi [64][32];      // 32KB
    __shared__ float4 spjb[16][32];      // 8KB
    __shared__ float  ssk [64][16];      // 4KB

    const float4* gpi  = (const float4*)(g_pi  + ((size_t)(b * N_ + i0)) * FOUT);
    const float4* gpjb = (const float4*)(g_pjb + ((size_t)(b * N_ + j0)) * FOUT);
    #pragma unroll
    for (int t = tid; t < 2048; t += 256)
        spi[t >> 5][t & 31] = gpi[t];
    #pragma unroll
    for (int t = tid; t < 512; t += 256)
        spjb[t >> 5][t & 31] = gpjb[t];
    #pragma unroll
    for (int t = tid; t < 1024; t += 256) {
        int ii = t >> 4, jj = t & 15;
        ssk[ii][jj] = sk[((size_t)(b * N_ + i0 + ii)) * N_ + j0 + jj];
    }
    __syncthreads();

    const int lane = tid & 31;
    const int w    = tid >> 5;           // warp 0..7 -> jj in {w, w+8}

    const float4 c0 = spjb[w][lane];
    const float4 c1 = spjb[w + 8][lane];

    float4 acc0 = make_float4(0.f, 0.f, 0.f, 0.f);
    float4 acc1 = make_float4(0.f, 0.f, 0.f, 0.f);

    float4* __restrict__ e4 = (float4*)edges;
    const size_t base = ((size_t)(b * N_ + i0) * N_ + j0) * 32 + lane;

    #pragma unroll 4
    for (int ii = 0; ii < 64; ii++) {
        float4 a  = spi[ii][lane];
        float  s0 = ssk[ii][w];
        float  s1 = ssk[ii][w + 8];
        float4 e0, e1;
        e0.x = (a.x + c0.x) * s0;  e0.y = (a.y + c0.y) * s0;
        e0.z = (a.z + c0.z) * s0;  e0.w = (a.w + c0.w) * s0;
        e1.x = (a.x + c1.x) * s1;  e1.y = (a.y + c1.y) * s1;
        e1.z = (a.z + c1.z) * s1;  e1.w = (a.w + c1.w) * s1;
        size_t rbase = base + (size_t)ii * (N_ * 32);
        __stcs(&e4[rbase + (size_t)w * 32],        e0);
        __stcs(&e4[rbase + (size_t)(w + 8) * 32],  e1);
        acc0.x += e0.x; acc0.y += e0.y; acc0.z += e0.z; acc0.w += e0.w;
        acc1.x += e1.x; acc1.y += e1.y; acc1.z += e1.z; acc1.w += e1.w;
    }

    // write partials: g_part[b][iy][j][f]  (FULL edge sums — nothing added later)
    float4* p4 = (float4*)g_part;
    size_t pbase = (((size_t)(b * NCH + iy) * N_) + j0) * 32 + lane;
    p4[pbase + (size_t)w * 32]       = acc0;
    p4[pbase + (size_t)(w + 8) * 32] = acc1;
}

// ---------------------------------------------------------------------------
// K3: fold partials (already complete edge sums), node_W GEMV + bias + h.
// 2 j-rows per block. grid = (N/2, B) = 1024 blocks, 128 threads (f).
// ---------------------------------------------------------------------------
__global__ __launch_bounds__(128) void k3_final(
    const float* __restrict__ nW, const float* __restrict__ nb,
    float* __restrict__ out1)
{
    const int b  = blockIdx.y;
    const int j0 = blockIdx.x * 2;
    const int f  = threadIdx.x;

    __shared__ float nn[2][FOUT];

    float acc0 = 0.f, acc1 = 0.f;
    #pragma unroll
    for (int c = 0; c < NCH; c++) {
        const float* pr = g_part + (((size_t)(b * NCH + c) * N_) + j0) * FOUT + f;
        acc0 += pr[0];
        acc1 += pr[FOUT];
    }
    nn[0][f] = acc0;
    nn[1][f] = acc1;
    __syncthreads();

    const float nbf = nb[f];
    float o0 = nbf, o1 = nbf;
    const float4* nwr = (const float4*)(nW + (size_t)f * FOUT);
    #pragma unroll 8
    for (int k = 0; k < 32; k++) {
        float4 w  = nwr[k];
        float4 n0 = ((const float4*)nn[0])[k];
        float4 n1 = ((const float4*)nn[1])[k];
        o0 += w.x*n0.x + w.y*n0.y + w.z*n0.z + w.w*n0.w;
        o1 += w.x*n1.x + w.y*n1.y + w.z*n1.z + w.w*n1.w;
    }

    const float* hr = g_h + ((size_t)(b * N_ + j0)) * FOUT;
    out1[((size_t)(b * N_ + j0))     * FOUT + f] = o0 + hr[f];
    out1[((size_t)(b * N_ + j0 + 1)) * FOUT + f] = o1 + hr[FOUT + f];
}

// ---------------------------------------------------------------------------
extern "C" void kernel_launch(void* const* d_in, const int* in_sizes, int n_in,
                              void* d_out, int out_size)
{
    const float* nodes = (const float*)d_in[0];
    const float* sk    = (const float*)d_in[1];
    const float* eW    = (const float*)d_in[2];
    const float* eb    = (const float*)d_in[3];
    const float* nW    = (const float*)d_in[4];
    const float* nb    = (const float*)d_in[5];
    const float* W0    = (const float*)d_in[6];
    const float* b0    = (const float*)d_in[7];
    const float* W1    = (const float*)d_in[8];
    const float* b1    = (const float*)d_in[9];
    const float* W2    = (const float*)d_in[10];
    const float* b2    = (const float*)d_in[11];

    float* out1  = (float*)d_out;                            // [B,N,F_OUT]
    float* edges = (float*)d_out + (size_t)B_ * N_ * FOUT;   // [B,N,N,F_OUT]

    k1_pernode<<<(B_ * N_) / 8, 128>>>(nodes, eW, eb, W0, b0, W1, b1, W2, b2);

    dim3 g2(N_ / 16, N_ / 64, B_);
    k2_edges<<<g2, 256>>>(sk, edges);

    dim3 g3(N_ / 2, B_);
    k3_final<<<g3, 128>>>(nW, nb, out1);
}